// round 8
// baseline (speedup 1.0000x reference)
#include <cuda_runtime.h>

#define N_NODES 500000
#define N_EDGES 16000000

// ---------------- scratch (device globals; no allocs allowed) ----------------
__device__ int       g_src[N_EDGES];     // 64 MB
__device__ int       g_dst[N_EDGES];     // 64 MB
__device__ unsigned  g_deg[N_NODES];     // 2 MB
__device__ float     g_dinv[N_NODES];    // 2 MB
__device__ float4    g_xw[N_NODES];      // 8 MB  (pre-scaled xw * dinv, 4-wide layers)
__device__ float4    g_agg[N_NODES];     // 8 MB  (accumulator, init = self term)
__device__ float2    g_xw2[N_NODES];     // 4 MB  (layer-3 pre-scaled, 2-wide)
__device__ int       g_is64;             // edge dtype flag (1 = int64, 0 = int32)

// ---------------- layout detection ----------------
// int64 little-endian node ids < 2^31  =>  every odd 32-bit word is 0.
// int32 layout => odd words are node indices (random in [0, 5e5)); 4096 samples
// all being zero has probability ~ (2e-6)^4096 ~ 0. One block, deterministic.
__global__ void k_detect(const int* __restrict__ e) {
    __shared__ int nz;
    if (threadIdx.x == 0) nz = 0;
    __syncthreads();
    int local = 0;
    #pragma unroll
    for (int m = 0; m < 16; m++) {
        // sample odd words within the first 32M 32-bit words (valid for both
        // layouts: int32 buffer has 32M words, int64 buffer has 64M words)
        int k = (int)((((unsigned)threadIdx.x * 16u + m) * 7919u) & (16u * 1024u * 1024u - 1u));
        if (e[2 * k + 1] != 0) local = 1;
    }
    if (local) atomicOr(&nz, 1);
    __syncthreads();
    if (threadIdx.x == 0) g_is64 = (nz == 0) ? 1 : 0;
}

// ---------------- kernels ----------------
__global__ void k_zero_deg() {
    int i = blockIdx.x * blockDim.x + threadIdx.x;
    if (i < N_NODES) g_deg[i] = 0u;
}

// Decode edge_index -> int32 src/dst arrays (handles int32 or int64 input),
// and count in-degree. 4 edges per thread, vectorized loads.
__global__ void k_prep_edges(const int* __restrict__ e) {
    int t = blockIdx.x * blockDim.x + threadIdx.x;   // covers edges 4t..4t+3
    if (4 * t >= N_EDGES) return;
    int4 s, d;
    if (g_is64) {
        // int64 layout: src row = words [0, 2E), dst row = words [2E, 4E)
        const int4* e4 = (const int4*)e;
        int4 a = e4[2 * t];                    // src edges 4t, 4t+1 (low words x,z)
        int4 b = e4[2 * t + 1];                // src edges 4t+2, 4t+3
        int4 c = e4[(N_EDGES / 2) + 2 * t];     // dst edges 4t, 4t+1
        int4 f = e4[(N_EDGES / 2) + 2 * t + 1]; // dst edges 4t+2, 4t+3
        s = make_int4(a.x, a.z, b.x, b.z);
        d = make_int4(c.x, c.z, f.x, f.z);
    } else {
        // int32 layout: src row = words [0, E), dst row = words [E, 2E)
        const int4* e4 = (const int4*)e;
        s = e4[t];
        d = e4[(N_EDGES / 4) + t];
    }
    ((int4*)g_src)[t] = s;
    ((int4*)g_dst)[t] = d;
    atomicAdd(&g_deg[d.x], 1u);
    atomicAdd(&g_deg[d.y], 1u);
    atomicAdd(&g_deg[d.z], 1u);
    atomicAdd(&g_deg[d.w], 1u);
}

__global__ void k_dinv() {
    int i = blockIdx.x * blockDim.x + threadIdx.x;
    if (i < N_NODES) g_dinv[i] = rsqrtf((float)g_deg[i] + 1.0f);
}

// Layer 1 node stage: xw = x @ W1 (2->4), store pre-scaled xws = xw*dinv,
// init agg with the self term (= xws, since the final scale multiplies by dinv again).
__global__ void k_node1(const float* __restrict__ x, const float* __restrict__ W1) {
    int i = blockIdx.x * blockDim.x + threadIdx.x;
    if (i >= N_NODES) return;
    float2 xi = ((const float2*)x)[i];
    float di = g_dinv[i];
    float4 r;
    r.x = (xi.x * W1[0] + xi.y * W1[4]) * di;
    r.y = (xi.x * W1[1] + xi.y * W1[5]) * di;
    r.z = (xi.x * W1[2] + xi.y * W1[6]) * di;
    r.w = (xi.x * W1[3] + xi.y * W1[7]) * di;
    g_xw[i]  = r;
    g_agg[i] = r;   // self-loop contribution (pre-scaled once; *dinv again later)
}

// Edge pass for 4-wide layers: agg[dst] += xws[src]. 4 edges/thread.
// Scalar float REDs (no return) — ptxas emits REDG.E.ADD.F32.
__global__ void k_edge4() {
    int t = blockIdx.x * blockDim.x + threadIdx.x;
    if (4 * t >= N_EDGES) return;
    const int4 s = ((const int4*)g_src)[t];
    const int4 d = ((const int4*)g_dst)[t];
    float4 v0 = g_xw[s.x];
    float4 v1 = g_xw[s.y];
    float4 v2 = g_xw[s.z];
    float4 v3 = g_xw[s.w];
    float* a0 = (float*)&g_agg[d.x];
    float* a1 = (float*)&g_agg[d.y];
    float* a2 = (float*)&g_agg[d.z];
    float* a3 = (float*)&g_agg[d.w];
    atomicAdd(a0 + 0, v0.x); atomicAdd(a0 + 1, v0.y);
    atomicAdd(a0 + 2, v0.z); atomicAdd(a0 + 3, v0.w);
    atomicAdd(a1 + 0, v1.x); atomicAdd(a1 + 1, v1.y);
    atomicAdd(a1 + 2, v1.z); atomicAdd(a1 + 3, v1.w);
    atomicAdd(a2 + 0, v2.x); atomicAdd(a2 + 1, v2.y);
    atomicAdd(a2 + 2, v2.z); atomicAdd(a2 + 3, v2.w);
    atomicAdd(a3 + 0, v3.x); atomicAdd(a3 + 1, v3.y);
    atomicAdd(a3 + 2, v3.z); atomicAdd(a3 + 3, v3.w);
}

// Layer 2 node stage: h = tanh(agg*dinv + b1); xws2 = (h@W2)*dinv; re-init agg.
__global__ void k_node2(const float* __restrict__ W2, const float* __restrict__ b1) {
    int i = blockIdx.x * blockDim.x + threadIdx.x;
    if (i >= N_NODES) return;
    float di = g_dinv[i];
    float4 a = g_agg[i];
    float hx = tanhf(a.x * di + b1[0]);
    float hy = tanhf(a.y * di + b1[1]);
    float hz = tanhf(a.z * di + b1[2]);
    float hw = tanhf(a.w * di + b1[3]);
    float4 r;
    r.x = (hx * W2[0] + hy * W2[4] + hz * W2[8]  + hw * W2[12]) * di;
    r.y = (hx * W2[1] + hy * W2[5] + hz * W2[9]  + hw * W2[13]) * di;
    r.z = (hx * W2[2] + hy * W2[6] + hz * W2[10] + hw * W2[14]) * di;
    r.w = (hx * W2[3] + hy * W2[7] + hz * W2[11] + hw * W2[15]) * di;
    g_xw[i]  = r;
    g_agg[i] = r;
}

// Layer 3 node stage: h = tanh(agg*dinv + b2); xws3 = (h@W3)*dinv (2-wide);
// initialize d_out with the self term (d_out is the layer-3 accumulator).
__global__ void k_node3(const float* __restrict__ W3, const float* __restrict__ b2,
                        float2* __restrict__ out) {
    int i = blockIdx.x * blockDim.x + threadIdx.x;
    if (i >= N_NODES) return;
    float di = g_dinv[i];
    float4 a = g_agg[i];
    float hx = tanhf(a.x * di + b2[0]);
    float hy = tanhf(a.y * di + b2[1]);
    float hz = tanhf(a.z * di + b2[2]);
    float hw = tanhf(a.w * di + b2[3]);
    float2 r;
    r.x = (hx * W3[0] + hy * W3[2] + hz * W3[4] + hw * W3[6]) * di;
    r.y = (hx * W3[1] + hy * W3[3] + hz * W3[5] + hw * W3[7]) * di;
    g_xw2[i] = r;
    out[i]   = r;   // self term; also un-poisons d_out
}

// Edge pass for the 2-wide final layer, accumulating straight into d_out.
__global__ void k_edge2(float2* __restrict__ out) {
    int t = blockIdx.x * blockDim.x + threadIdx.x;
    if (4 * t >= N_EDGES) return;
    const int4 s = ((const int4*)g_src)[t];
    const int4 d = ((const int4*)g_dst)[t];
    float2 v0 = g_xw2[s.x];
    float2 v1 = g_xw2[s.y];
    float2 v2 = g_xw2[s.z];
    float2 v3 = g_xw2[s.w];
    float* o0 = (float*)&out[d.x];
    float* o1 = (float*)&out[d.y];
    float* o2 = (float*)&out[d.z];
    float* o3 = (float*)&out[d.w];
    atomicAdd(o0 + 0, v0.x); atomicAdd(o0 + 1, v0.y);
    atomicAdd(o1 + 0, v1.x); atomicAdd(o1 + 1, v1.y);
    atomicAdd(o2 + 0, v2.x); atomicAdd(o2 + 1, v2.y);
    atomicAdd(o3 + 0, v3.x); atomicAdd(o3 + 1, v3.y);
}

// Final scale + bias: out_i = agg_i * dinv_i + b3 (no tanh on last layer).
__global__ void k_finalize(float2* __restrict__ out, const float* __restrict__ b3) {
    int i = blockIdx.x * blockDim.x + threadIdx.x;
    if (i >= N_NODES) return;
    float di = g_dinv[i];
    float2 a = out[i];
    a.x = a.x * di + b3[0];
    a.y = a.y * di + b3[1];
    out[i] = a;
}

// ---------------- launch ----------------
extern "C" void kernel_launch(void* const* d_in, const int* in_sizes, int n_in,
                              void* d_out, int out_size) {
    const float* x  = (const float*)d_in[0];
    const int*   e  = (const int*)d_in[1];    // edge_index [2, E], int32 OR int64 (auto-detected)
    const float* W1 = (const float*)d_in[2];
    const float* b1 = (const float*)d_in[3];
    const float* W2 = (const float*)d_in[4];
    const float* b2 = (const float*)d_in[5];
    const float* W3 = (const float*)d_in[6];
    const float* b3 = (const float*)d_in[7];
    float2* out = (float2*)d_out;

    const int TB = 256;
    const int gNode  = (N_NODES + TB - 1) / TB;
    const int gEdge4 = (N_EDGES / 4 + TB - 1) / TB;

    k_detect<<<1, 256>>>(e);
    k_zero_deg<<<gNode, TB>>>();
    k_prep_edges<<<gEdge4, TB>>>(e);
    k_dinv<<<gNode, TB>>>();

    k_node1<<<gNode, TB>>>(x, W1);
    k_edge4<<<gEdge4, TB>>>();

    k_node2<<<gNode, TB>>>(W2, b1);
    k_edge4<<<gEdge4, TB>>>();

    k_node3<<<gNode, TB>>>(W3, b2, out);
    k_edge2<<<gEdge4, TB>>>(out);
    k_finalize<<<gNode, TB>>>(out, b3);
}

// round 9
// speedup vs baseline: 2.0279x; 2.0279x over previous
#include <cuda_runtime.h>

#define N_NODES 500000
#define N_EDGES 16000000

// ---------------- scratch (device globals; no allocs allowed) ----------------
__device__ int       g_src[N_EDGES];     // 64 MB (used only for int64 input)
__device__ int       g_dst[N_EDGES];     // 64 MB (used only for int64 input)
__device__ unsigned  g_deg[N_NODES];     // 2 MB
__device__ float     g_dinv[N_NODES];    // 2 MB
__device__ float4    g_xw[N_NODES];      // 8 MB  (pre-scaled xw * dinv, 4-wide layers)
__device__ float4    g_agg[N_NODES];     // 8 MB  (accumulator, init = self term)
__device__ float2    g_xw2[N_NODES];     // 4 MB  (layer-3 pre-scaled, 2-wide)
__device__ int       g_is64;             // edge dtype flag (1 = int64, 0 = int32)

// ---------------- vector red helpers (sm_90+; addresses now guaranteed sane) --
__device__ __forceinline__ void red_add_f4(float4* p, float4 v) {
    asm volatile("red.global.add.v4.f32 [%0], {%1,%2,%3,%4};"
                 :: "l"(p), "f"(v.x), "f"(v.y), "f"(v.z), "f"(v.w) : "memory");
}
__device__ __forceinline__ void red_add_f2(float2* p, float2 v) {
    asm volatile("red.global.add.v2.f32 [%0], {%1,%2};"
                 :: "l"(p), "f"(v.x), "f"(v.y) : "memory");
}

// ---------------- layout detection ----------------
// int64 little-endian node ids < 2^31  =>  every odd 32-bit word is 0.
// int32 layout => odd words are node indices; 4096 zero samples ~ impossible.
__global__ void k_detect(const int* __restrict__ e) {
    __shared__ int nz;
    if (threadIdx.x == 0) nz = 0;
    __syncthreads();
    int local = 0;
    #pragma unroll
    for (int m = 0; m < 16; m++) {
        int k = (int)((((unsigned)threadIdx.x * 16u + m) * 7919u) & (16u * 1024u * 1024u - 1u));
        if (e[2 * k + 1] != 0) local = 1;
    }
    if (local) atomicOr(&nz, 1);
    __syncthreads();
    if (threadIdx.x == 0) g_is64 = (nz == 0) ? 1 : 0;
}

// ---------------- kernels ----------------
__global__ void k_zero_deg() {
    int i = blockIdx.x * blockDim.x + threadIdx.x;
    if (i < N_NODES) g_deg[i] = 0u;
}

// Degree count (+ int64->int32 decode into scratch only when needed).
// For int32 input the edge kernels read straight from the input buffer,
// so this kernel does NO scratch writes on that path.
__global__ void k_prep_edges(const int* __restrict__ e) {
    int t = blockIdx.x * blockDim.x + threadIdx.x;   // covers edges 4t..4t+3
    if (4 * t >= N_EDGES) return;
    int4 d;
    if (g_is64) {
        const int4* e4 = (const int4*)e;
        int4 a = e4[2 * t];
        int4 b = e4[2 * t + 1];
        int4 c = e4[(N_EDGES / 2) + 2 * t];
        int4 f = e4[(N_EDGES / 2) + 2 * t + 1];
        ((int4*)g_src)[t] = make_int4(a.x, a.z, b.x, b.z);
        d = make_int4(c.x, c.z, f.x, f.z);
        ((int4*)g_dst)[t] = d;
    } else {
        d = ((const int4*)e)[(N_EDGES / 4) + t];
    }
    atomicAdd(&g_deg[d.x], 1u);
    atomicAdd(&g_deg[d.y], 1u);
    atomicAdd(&g_deg[d.z], 1u);
    atomicAdd(&g_deg[d.w], 1u);
}

__global__ void k_dinv() {
    int i = blockIdx.x * blockDim.x + threadIdx.x;
    if (i < N_NODES) g_dinv[i] = rsqrtf((float)g_deg[i] + 1.0f);
}

// Layer 1 node stage: xw = x @ W1 (2->4), store pre-scaled xws = xw*dinv,
// init agg with the self term (= xws; the final scale multiplies by dinv again).
__global__ void k_node1(const float* __restrict__ x, const float* __restrict__ W1) {
    int i = blockIdx.x * blockDim.x + threadIdx.x;
    if (i >= N_NODES) return;
    float2 xi = ((const float2*)x)[i];
    float di = g_dinv[i];
    float4 r;
    r.x = (xi.x * W1[0] + xi.y * W1[4]) * di;
    r.y = (xi.x * W1[1] + xi.y * W1[5]) * di;
    r.z = (xi.x * W1[2] + xi.y * W1[6]) * di;
    r.w = (xi.x * W1[3] + xi.y * W1[7]) * di;
    g_xw[i]  = r;
    g_agg[i] = r;
}

// Edge pass for 4-wide layers: agg[dst] += xws[src]. 4 edges/thread.
// Vector red.global.add.v4.f32: one red-op per edge instead of four.
__global__ void k_edge4(const int* __restrict__ e) {
    int t = blockIdx.x * blockDim.x + threadIdx.x;
    if (4 * t >= N_EDGES) return;
    int4 s, d;
    if (g_is64) {
        s = ((const int4*)g_src)[t];
        d = ((const int4*)g_dst)[t];
    } else {
        s = ((const int4*)e)[t];
        d = ((const int4*)e)[(N_EDGES / 4) + t];
    }
    float4 v0 = g_xw[s.x];
    float4 v1 = g_xw[s.y];
    float4 v2 = g_xw[s.z];
    float4 v3 = g_xw[s.w];
    red_add_f4(&g_agg[d.x], v0);
    red_add_f4(&g_agg[d.y], v1);
    red_add_f4(&g_agg[d.z], v2);
    red_add_f4(&g_agg[d.w], v3);
}

// Layer 2 node stage: h = tanh(agg*dinv + b1); xws2 = (h@W2)*dinv; re-init agg.
__global__ void k_node2(const float* __restrict__ W2, const float* __restrict__ b1) {
    int i = blockIdx.x * blockDim.x + threadIdx.x;
    if (i >= N_NODES) return;
    float di = g_dinv[i];
    float4 a = g_agg[i];
    float hx = tanhf(a.x * di + b1[0]);
    float hy = tanhf(a.y * di + b1[1]);
    float hz = tanhf(a.z * di + b1[2]);
    float hw = tanhf(a.w * di + b1[3]);
    float4 r;
    r.x = (hx * W2[0] + hy * W2[4] + hz * W2[8]  + hw * W2[12]) * di;
    r.y = (hx * W2[1] + hy * W2[5] + hz * W2[9]  + hw * W2[13]) * di;
    r.z = (hx * W2[2] + hy * W2[6] + hz * W2[10] + hw * W2[14]) * di;
    r.w = (hx * W2[3] + hy * W2[7] + hz * W2[11] + hw * W2[15]) * di;
    g_xw[i]  = r;
    g_agg[i] = r;
}

// Layer 3 node stage: h = tanh(agg*dinv + b2); xws3 = (h@W3)*dinv (2-wide);
// initialize d_out with the self term (d_out is the layer-3 accumulator).
__global__ void k_node3(const float* __restrict__ W3, const float* __restrict__ b2,
                        float2* __restrict__ out) {
    int i = blockIdx.x * blockDim.x + threadIdx.x;
    if (i >= N_NODES) return;
    float di = g_dinv[i];
    float4 a = g_agg[i];
    float hx = tanhf(a.x * di + b2[0]);
    float hy = tanhf(a.y * di + b2[1]);
    float hz = tanhf(a.z * di + b2[2]);
    float hw = tanhf(a.w * di + b2[3]);
    float2 r;
    r.x = (hx * W3[0] + hy * W3[2] + hz * W3[4] + hw * W3[6]) * di;
    r.y = (hx * W3[1] + hy * W3[3] + hz * W3[5] + hw * W3[7]) * di;
    g_xw2[i] = r;
    out[i]   = r;
}

// Edge pass for the 2-wide final layer, accumulating straight into d_out.
__global__ void k_edge2(const int* __restrict__ e, float2* __restrict__ out) {
    int t = blockIdx.x * blockDim.x + threadIdx.x;
    if (4 * t >= N_EDGES) return;
    int4 s, d;
    if (g_is64) {
        s = ((const int4*)g_src)[t];
        d = ((const int4*)g_dst)[t];
    } else {
        s = ((const int4*)e)[t];
        d = ((const int4*)e)[(N_EDGES / 4) + t];
    }
    float2 v0 = g_xw2[s.x];
    float2 v1 = g_xw2[s.y];
    float2 v2 = g_xw2[s.z];
    float2 v3 = g_xw2[s.w];
    red_add_f2(&out[d.x], v0);
    red_add_f2(&out[d.y], v1);
    red_add_f2(&out[d.z], v2);
    red_add_f2(&out[d.w], v3);
}

// Final scale + bias: out_i = agg_i * dinv_i + b3 (no tanh on last layer).
__global__ void k_finalize(float2* __restrict__ out, const float* __restrict__ b3) {
    int i = blockIdx.x * blockDim.x + threadIdx.x;
    if (i >= N_NODES) return;
    float di = g_dinv[i];
    float2 a = out[i];
    a.x = a.x * di + b3[0];
    a.y = a.y * di + b3[1];
    out[i] = a;
}

// ---------------- launch ----------------
extern "C" void kernel_launch(void* const* d_in, const int* in_sizes, int n_in,
                              void* d_out, int out_size) {
    const float* x  = (const float*)d_in[0];
    const int*   e  = (const int*)d_in[1];    // edge_index [2, E], int32 OR int64 (auto-detected)
    const float* W1 = (const float*)d_in[2];
    const float* b1 = (const float*)d_in[3];
    const float* W2 = (const float*)d_in[4];
    const float* b2 = (const float*)d_in[5];
    const float* W3 = (const float*)d_in[6];
    const float* b3 = (const float*)d_in[7];
    float2* out = (float2*)d_out;

    const int TB = 256;
    const int gNode  = (N_NODES + TB - 1) / TB;
    const int gEdge4 = (N_EDGES / 4 + TB - 1) / TB;

    k_detect<<<1, 256>>>(e);
    k_zero_deg<<<gNode, TB>>>();
    k_prep_edges<<<gEdge4, TB>>>(e);
    k_dinv<<<gNode, TB>>>();

    k_node1<<<gNode, TB>>>(x, W1);
    k_edge4<<<gEdge4, TB>>>(e);

    k_node2<<<gNode, TB>>>(W2, b1);
    k_edge4<<<gEdge4, TB>>>(e);

    k_node3<<<gNode, TB>>>(W3, b2, out);
    k_edge2<<<gEdge4, TB>>>(e, out);
    k_finalize<<<gNode, TB>>>(out, b3);
}